// round 7
// baseline (speedup 1.0000x reference)
#include <cuda_runtime.h>
#include <cuda_bf16.h>
#include <math.h>
#include <stdint.h>

#define TT 256
#define BB 64
#define DD 1024
#define HH 2048

#define GRID 128
#define SCTHREADS 512
#define NBD 8            // n-blocks (each 256 wide)
#define KBD 16           // k-blocks (each 128 deep)
#define NSL 256
#define KSL 128
#define STEP_ELEMS (BB * HH)   // 131072

typedef unsigned long long ull;

// Scratch (no cudaMalloc allowed)
__device__ __align__(16) float g_xproj[(size_t)TT * BB * HH];     // 128 MB
__device__ __align__(16) float g_part[(size_t)KBD * BB * HH];     // 8 MB
__device__ __align__(16) __nv_bfloat16 g_xhi[(size_t)TT * BB * DD];
__device__ __align__(16) __nv_bfloat16 g_xlo[(size_t)TT * BB * DD];
__device__ __align__(16) __nv_bfloat16 g_whi[(size_t)DD * HH];
__device__ __align__(16) __nv_bfloat16 g_wlo[(size_t)DD * HH];
__device__ unsigned g_arrive;    // zero-init; self-resetting
__device__ unsigned g_release;   // monotonic epoch counter

// ---- packed f32x2 helpers ---------------------------------------------------
__device__ __forceinline__ ull pack2(float x, float y) {
    ull r; asm("mov.b64 %0, {%1, %2};" : "=l"(r) : "f"(x), "f"(y)); return r;
}
__device__ __forceinline__ void unpack2(ull v, float& x, float& y) {
    asm("mov.b64 {%0, %1}, %2;" : "=f"(x), "=f"(y) : "l"(v));
}
__device__ __forceinline__ void fma2(ull& d, ull a, ull b) {
    asm("fma.rn.f32x2 %0, %1, %2, %0;" : "+l"(d) : "l"(a), "l"(b));
}
__device__ __forceinline__ uint32_t smem_to_u32(const void* p) {
    uint32_t a;
    asm("{ .reg .u64 t; cvta.to.shared.u64 t, %1; cvt.u32.u64 %0, t; }"
        : "=r"(a) : "l"(p));
    return a;
}

// ---- mma.sync helpers (sm_80-era PTX, compiles for compute_103) --------------
__device__ __forceinline__ void ldsm_x4(uint32_t addr, uint32_t* r) {
    asm volatile("ldmatrix.sync.aligned.m8n8.x4.shared.b16 {%0,%1,%2,%3}, [%4];"
                 : "=r"(r[0]), "=r"(r[1]), "=r"(r[2]), "=r"(r[3]) : "r"(addr));
}
__device__ __forceinline__ void ldsm_x4_t(uint32_t addr, uint32_t* r) {
    asm volatile("ldmatrix.sync.aligned.m8n8.x4.trans.shared.b16 {%0,%1,%2,%3}, [%4];"
                 : "=r"(r[0]), "=r"(r[1]), "=r"(r[2]), "=r"(r[3]) : "r"(addr));
}
__device__ __forceinline__ void mma_bf16(float* c, const uint32_t* a,
                                         uint32_t b0, uint32_t b1) {
    asm volatile(
        "mma.sync.aligned.m16n8k16.row.col.f32.bf16.bf16.f32 "
        "{%0,%1,%2,%3}, {%4,%5,%6,%7}, {%8,%9}, {%0,%1,%2,%3};"
        : "+f"(c[0]), "+f"(c[1]), "+f"(c[2]), "+f"(c[3])
        : "r"(a[0]), "r"(a[1]), "r"(a[2]), "r"(a[3]), "r"(b0), "r"(b1));
}

// ---- grid barrier with release/acquire ordering ------------------------------
__device__ __forceinline__ void grid_barrier(unsigned& epoch) {
    __syncthreads();
    if (threadIdx.x == 0) {
        __threadfence();
        unsigned a = atomicAdd(&g_arrive, 1u);
        if (a == GRID - 1) {
            atomicExch(&g_arrive, 0u);
            __threadfence();
            atomicAdd(&g_release, 1u);
        } else {
            unsigned r;
            do {
                asm volatile("ld.acquire.gpu.u32 %0, [%1];"
                             : "=r"(r) : "l"(&g_release));
            } while (r == epoch);
        }
        __threadfence();
    }
    epoch += 1;
    __syncthreads();
}

extern __shared__ float smem[];

// -----------------------------------------------------------------------------
// Persistent scan kernel (512 threads): all 256 recurrence steps in one launch.
// CTA (nb, kb) keeps W_hh[kb*128:+128, nb*256:+256] resident in SMEM.
// -----------------------------------------------------------------------------
__global__ void __launch_bounds__(SCTHREADS) scan_kernel(
    const float* __restrict__ state,
    const float* __restrict__ W,
    float* __restrict__ out)
{
    float* ws = smem;                       // [KSL][NSL]
    float* hsb = smem + KSL * NSL;          // [2][64][68]
    const int HPAD = 68;
    const int HBUF = 64 * HPAD;

    const int tid = threadIdx.x;
    const int cta = blockIdx.x;
    const int nb = cta & (NBD - 1);
    const int kb = cta >> 3;
    const int nbase = nb * NSL;
    const int k0 = kb * KSL;
    const int tx = tid & 15;                // n: 4 quads at q*64 + tx*4
    const int ty = tid >> 4;                // 0..31 -> m rows ty*2, ty*2+1

    // load resident W slice (once)
#pragma unroll
    for (int i = 0; i < 16; i++) {
        int idx = i * SCTHREADS + tid;      // 0..8191 float4s
        int k = idx >> 6;
        int c4 = (idx & 63) * 4;
        *(float4*)&ws[k * NSL + c4] =
            *(const float4*)&W[(size_t)(k0 + k) * HH + nbase + c4];
    }
    __syncthreads();

    unsigned epoch;
    {
        unsigned r;
        asm volatile("ld.acquire.gpu.u32 %0, [%1];" : "=r"(r) : "l"(&g_release));
        epoch = r;
    }

    // epilogue mapping (first 32768 of 65536 threads handle one float4 each)
    const int g = cta * SCTHREADS + tid;
    const int em = g >> 9;
    const int ec4 = (g & 511) * 4;
    const size_t eoff = (size_t)em * HH + ec4;
    const bool edo = (g < STEP_ELEMS / 4);

    for (int t = 0; t < TT; t++) {
        const float* hp = (t == 0) ? state : (out + (size_t)(t - 1) * STEP_ELEMS);

        ull acc[2][8];
#pragma unroll
        for (int i = 0; i < 2; i++)
#pragma unroll
            for (int j = 0; j < 8; j++) acc[i][j] = 0ULL;

        float4 hreg[2];
#pragma unroll
        for (int i = 0; i < 2; i++) {
            int idx = i * SCTHREADS + tid;  // 0..1023
            int m = idx >> 4, kq4 = (idx & 15) * 4;
            hreg[i] = __ldcg((const float4*)&hp[(size_t)m * HH + k0 + kq4]);
        }

        int buf = 0;
        for (int c = 0; c < KSL / 64; c++) {     // 2 chunks
#pragma unroll
            for (int i = 0; i < 2; i++) {
                int idx = i * SCTHREADS + tid;
                int m = idx >> 4, kq4 = (idx & 15) * 4;
                *(float4*)&hsb[buf * HBUF + m * HPAD + kq4] = hreg[i];
            }
            __syncthreads();
            if (c + 1 < KSL / 64) {
#pragma unroll
                for (int i = 0; i < 2; i++) {
                    int idx = i * SCTHREADS + tid;
                    int m = idx >> 4, kq4 = (idx & 15) * 4;
                    hreg[i] = __ldcg((const float4*)&hp[(size_t)m * HH + k0 + (c + 1) * 64 + kq4]);
                }
            }
            const float* hb = hsb + buf * HBUF + (ty * 2) * HPAD;
            const float* wrow = ws + (c * 64) * NSL + tx * 4;
#pragma unroll 8
            for (int kk = 0; kk < 64; kk++) {
                const float* wr = wrow + kk * NSL;
                ulonglong2 b0 = *(const ulonglong2*)(wr);
                ulonglong2 b1 = *(const ulonglong2*)(wr + 64);
                ulonglong2 b2 = *(const ulonglong2*)(wr + 128);
                ulonglong2 b3 = *(const ulonglong2*)(wr + 192);
                float a0 = hb[kk];
                float a1 = hb[HPAD + kk];
                ull A0 = pack2(a0, a0), A1 = pack2(a1, a1);
#define FM(i, A)                                    \
                fma2(acc[i][0], A, b0.x); fma2(acc[i][1], A, b0.y); \
                fma2(acc[i][2], A, b1.x); fma2(acc[i][3], A, b1.y); \
                fma2(acc[i][4], A, b2.x); fma2(acc[i][5], A, b2.y); \
                fma2(acc[i][6], A, b3.x); fma2(acc[i][7], A, b3.y)
                FM(0, A0); FM(1, A1);
#undef FM
            }
            __syncthreads();
            buf ^= 1;
        }

        // write partial tile [64 x 256] to g_part[kb]
        float* P = g_part + (size_t)kb * STEP_ELEMS;
#pragma unroll
        for (int i = 0; i < 2; i++) {
            const int m = ty * 2 + i;
#pragma unroll
            for (int q = 0; q < 4; q++) {
                float4 v;
                unpack2(acc[i][2 * q + 0], v.x, v.y);
                unpack2(acc[i][2 * q + 1], v.z, v.w);
                *(float4*)&P[(size_t)m * HH + nbase + q * 64 + tx * 4] = v;
            }
        }
        grid_barrier(epoch);

        // distributed epilogue: reduce 16 partials + x_proj, tanh -> out[t]
        if (edo) {
            float4 s = __ldcg((const float4*)&g_part[eoff]);
#pragma unroll
            for (int k2 = 1; k2 < KBD; k2++) {
                float4 p = __ldcg((const float4*)&g_part[(size_t)k2 * STEP_ELEMS + eoff]);
                s.x += p.x; s.y += p.y; s.z += p.z; s.w += p.w;
            }
            const float4 xv = *(const float4*)&g_xproj[(size_t)t * STEP_ELEMS + eoff];
            float4 r;
            r.x = tanhf(s.x + xv.x);
            r.y = tanhf(s.y + xv.y);
            r.z = tanhf(s.z + xv.z);
            r.w = tanhf(s.w + xv.w);
            *(float4*)&out[(size_t)t * STEP_ELEMS + eoff] = r;
            if (t == TT - 1)
                *(float4*)&out[(size_t)TT * STEP_ELEMS + eoff] = r;   // final_state
        }
        grid_barrier(epoch);
    }
}

// -----------------------------------------------------------------------------
// Elementwise bf16 hi/lo split: hi = bf16(x), lo = bf16(x - hi)
// -----------------------------------------------------------------------------
__global__ void __launch_bounds__(256) convert_split(
    const float* __restrict__ src,
    __nv_bfloat16* __restrict__ hi,
    __nv_bfloat16* __restrict__ lo)
{
    const int i = blockIdx.x * 256 + threadIdx.x;
    float4 v = ((const float4*)src)[i];
    float s[4] = {v.x, v.y, v.z, v.w};
    __nv_bfloat16 h[4], l[4];
#pragma unroll
    for (int j = 0; j < 4; j++) {
        h[j] = __float2bfloat16(s[j]);
        l[j] = __float2bfloat16(s[j] - __bfloat162float(h[j]));
    }
    __nv_bfloat162 h01 = __halves2bfloat162(h[0], h[1]);
    __nv_bfloat162 h23 = __halves2bfloat162(h[2], h[3]);
    __nv_bfloat162 l01 = __halves2bfloat162(l[0], l[1]);
    __nv_bfloat162 l23 = __halves2bfloat162(l[2], l[3]);
    ((uint2*)hi)[i] = make_uint2(*(uint32_t*)&h01, *(uint32_t*)&h23);
    ((uint2*)lo)[i] = make_uint2(*(uint32_t*)&l01, *(uint32_t*)&l23);
}

// -----------------------------------------------------------------------------
// x_proj via mma.sync bf16-split: D = Xhi*Whi + Xhi*Wlo + Xlo*Whi (+bias)
// CTA tile [128m x 128n], 8 warps (2m x 4n), warp tile 64x32, k-chunk 32.
// -----------------------------------------------------------------------------
#define APAD 40    // bf16 per A smem row (80 B, conflict-free ldmatrix)
#define BPAD 136   // bf16 per B smem row (272 B, conflict-free ldmatrix)

__global__ void __launch_bounds__(256) xproj_mma(
    const __nv_bfloat16* __restrict__ Xhi,
    const __nv_bfloat16* __restrict__ Xlo,
    const __nv_bfloat16* __restrict__ Whi,
    const __nv_bfloat16* __restrict__ Wlo,
    const float* __restrict__ bias)
{
    __shared__ __align__(16) __nv_bfloat16 sa[2][128 * APAD];   // hi, lo
    __shared__ __align__(16) __nv_bfloat16 sb[2][32 * BPAD];

    const int tid = threadIdx.x;
    const int wid = tid >> 5;
    const int lane = tid & 31;
    const int nbase = blockIdx.x * 128;
    const int mbase = blockIdx.y * 128;
    const int wm = (wid & 1) * 64;
    const int wn = (wid >> 1) * 32;

    float c[4][4][4];
#pragma unroll
    for (int mi = 0; mi < 4; mi++)
#pragma unroll
        for (int j = 0; j < 4; j++)
#pragma unroll
            for (int q = 0; q < 4; q++) c[mi][j][q] = 0.0f;

    // gmem staging indices (uint4 = 8 bf16)
    const int ar = tid >> 1, ac8 = (tid & 1) * 8 + 0;   // not used; computed per-iter
    (void)ar; (void)ac8;

    uint4 pa[2][2], pb[2][2];
    const __nv_bfloat16* Xs[2] = {Xhi, Xlo};
    const __nv_bfloat16* Ws[2] = {Whi, Wlo};

    // prefetch chunk 0
#pragma unroll
    for (int v = 0; v < 2; v++) {
#pragma unroll
        for (int it = 0; it < 2; it++) {
            int idx = it * 256 + tid;            // 0..511
            int r = idx >> 2, c8 = (idx & 3) * 8;
            pa[v][it] = *(const uint4*)&Xs[v][(size_t)(mbase + r) * DD + c8];
            int kr = idx >> 4, n8 = (idx & 15) * 8;
            pb[v][it] = *(const uint4*)&Ws[v][(size_t)kr * HH + nbase + n8];
        }
    }

    // ldmatrix smem addresses (fixed per thread)
    const int lrow = lane & 15;
    const int lcolq = lane >> 4;   // 0 or 1

    for (int ch = 0; ch < DD / 32; ch++) {       // 32 chunks of k=32
#pragma unroll
        for (int v = 0; v < 2; v++) {
#pragma unroll
            for (int it = 0; it < 2; it++) {
                int idx = it * 256 + tid;
                int r = idx >> 2, c8 = (idx & 3) * 8;
                *(uint4*)&sa[v][r * APAD + c8] = pa[v][it];
                int kr = idx >> 4, n8 = (idx & 15) * 8;
                *(uint4*)&sb[v][kr * BPAD + n8] = pb[v][it];
            }
        }
        __syncthreads();
        if (ch + 1 < DD / 32) {
            const int kc = (ch + 1) * 32;
#pragma unroll
            for (int v = 0; v < 2; v++) {
#pragma unroll
                for (int it = 0; it < 2; it++) {
                    int idx = it * 256 + tid;
                    int r = idx >> 2, c8 = (idx & 3) * 8;
                    pa[v][it] = *(const uint4*)&Xs[v][(size_t)(mbase + r) * DD + kc + c8];
                    int kr = idx >> 4, n8 = (idx & 15) * 8;
                    pb[v][it] = *(const uint4*)&Ws[v][(size_t)(kc + kr) * HH + nbase + n8];
                }
            }
        }

#pragma unroll
        for (int ks = 0; ks < 2; ks++) {         // two k16 steps
            uint32_t ah[4][4], al[4][4];
#pragma unroll
            for (int mi = 0; mi < 4; mi++) {
                uint32_t off = (uint32_t)((wm + mi * 16 + lrow) * APAD +
                                          ks * 16 + lcolq * 8) * 2;
                ldsm_x4(smem_to_u32(&sa[0][0]) + off, ah[mi]);
                ldsm_x4(smem_to_u32(&sa[1][0]) + off, al[mi]);
            }
            uint32_t bh[2][4], bl[2][4];
#pragma unroll
            for (int np = 0; np < 2; np++) {
                uint32_t off = (uint32_t)((ks * 16 + lrow) * BPAD +
                                          wn + np * 16 + lcolq * 8) * 2;
                ldsm_x4_t(smem_to_u32(&sb[0][0]) + off, bh[np]);
                ldsm_x4_t(smem_to_u32(&sb[1][0]) + off, bl[np]);
            }
#pragma unroll
            for (int mi = 0; mi < 4; mi++) {
#pragma unroll
                for (int j = 0; j < 4; j++) {
                    const int np = j >> 1, pr = (j & 1) * 2;
                    mma_bf16(c[mi][j], ah[mi], bh[np][pr], bh[np][pr + 1]);
                    mma_bf16(c[mi][j], ah[mi], bl[np][pr], bl[np][pr + 1]);
                    mma_bf16(c[mi][j], al[mi], bh[np][pr], bh[np][pr + 1]);
                }
            }
        }
        __syncthreads();
    }

    // epilogue: c[mi][j] -> g_xproj (+bias)
#pragma unroll
    for (int mi = 0; mi < 4; mi++) {
        const int row0 = mbase + wm + mi * 16 + (lane >> 2);
#pragma unroll
        for (int j = 0; j < 4; j++) {
            const int col = nbase + wn + j * 8 + (lane & 3) * 2;
            const float b0 = __ldg(&bias[col]);
            const float b1 = __ldg(&bias[col + 1]);
            float2 v0 = make_float2(c[mi][j][0] + b0, c[mi][j][1] + b1);
            float2 v1 = make_float2(c[mi][j][2] + b0, c[mi][j][3] + b1);
            *(float2*)&g_xproj[(size_t)row0 * HH + col] = v0;
            *(float2*)&g_xproj[(size_t)(row0 + 8) * HH + col] = v1;
        }
    }
}

extern "C" void kernel_launch(void* const* d_in, const int* in_sizes, int n_in,
                              void* d_out, int out_size)
{
    (void)in_sizes; (void)n_in; (void)out_size;
    const float* inputs = (const float*)d_in[0];   // [T,B,D]
    const float* state  = (const float*)d_in[1];   // [B,H]
    const float* W_xh   = (const float*)d_in[2];   // [D,H]
    const float* W_hh   = (const float*)d_in[3];   // [H,H]
    const float* b_h    = (const float*)d_in[4];   // [H]
    float* out = (float*)d_out;   // outputs [T,B,H] then final_state [B,H]

    const int sc_smem = (KSL * NSL + 2 * 64 * 68) * sizeof(float);  // 165888
    cudaFuncSetAttribute(scan_kernel, cudaFuncAttributeMaxDynamicSharedMemorySize,
                         sc_smem);

    __nv_bfloat16 *xhi, *xlo, *whi, *wlo;
    cudaGetSymbolAddress((void**)&xhi, g_xhi);
    cudaGetSymbolAddress((void**)&xlo, g_xlo);
    cudaGetSymbolAddress((void**)&whi, g_whi);
    cudaGetSymbolAddress((void**)&wlo, g_wlo);

    // 0) bf16 hi/lo splits of X and W_xh
    convert_split<<<(TT * BB * DD / 4) / 256, 256>>>(inputs, xhi, xlo);
    convert_split<<<(DD * HH / 4) / 256, 256>>>(W_xh, whi, wlo);

    // 1) x_proj via tensor cores (mma.sync bf16-split)
    xproj_mma<<<dim3(HH / 128, (TT * BB) / 128), 256>>>(xhi, xlo, whi, wlo, b_h);

    // 2) persistent scan: all 256 steps in one launch
    scan_kernel<<<GRID, SCTHREADS, sc_smem>>>(state, W_hh, out);
}

// round 8
// speedup vs baseline: 1.4160x; 1.4160x over previous
#include <cuda_runtime.h>
#include <cuda_bf16.h>
#include <math.h>
#include <stdint.h>

#define TT 256
#define BB 64
#define DD 1024
#define HH 2048

#define GRID 128
#define SCTHREADS 256
#define NBD 8            // n-blocks (each 256 wide)
#define KBD 16           // k-blocks (each 128 deep)
#define NSL 256
#define KSL 128
#define STEP_ELEMS (BB * HH)   // 131072

typedef unsigned long long ull;

// Scratch (no cudaMalloc allowed)
__device__ __align__(16) float g_xproj[(size_t)TT * BB * HH];     // 128 MB
__device__ __align__(16) float g_part[(size_t)KBD * BB * HH];     // 8 MB
__device__ __align__(16) __nv_bfloat16 g_xhi[(size_t)TT * BB * DD];
__device__ __align__(16) __nv_bfloat16 g_xlo[(size_t)TT * BB * DD];
__device__ __align__(16) __nv_bfloat16 g_whi[(size_t)DD * HH];
__device__ __align__(16) __nv_bfloat16 g_wlo[(size_t)DD * HH];
__device__ unsigned g_count;     // monotonic arrival counter (zeroed per launch)

// ---- packed f32x2 helpers ---------------------------------------------------
__device__ __forceinline__ ull pack2(float x, float y) {
    ull r; asm("mov.b64 %0, {%1, %2};" : "=l"(r) : "f"(x), "f"(y)); return r;
}
__device__ __forceinline__ void unpack2(ull v, float& x, float& y) {
    asm("mov.b64 {%0, %1}, %2;" : "=f"(x), "=f"(y) : "l"(v));
}
__device__ __forceinline__ void fma2(ull& d, ull a, ull b) {
    asm("fma.rn.f32x2 %0, %1, %2, %0;" : "+l"(d) : "l"(a), "l"(b));
}
__device__ __forceinline__ uint32_t smem_to_u32(const void* p) {
    uint32_t a;
    asm("{ .reg .u64 t; cvta.to.shared.u64 t, %1; cvt.u32.u64 %0, t; }"
        : "=r"(a) : "l"(p));
    return a;
}

// ---- mma.sync helpers (sm_80-era PTX, compiles for compute_103) --------------
__device__ __forceinline__ void ldsm_x4(uint32_t addr, uint32_t* r) {
    asm volatile("ldmatrix.sync.aligned.m8n8.x4.shared.b16 {%0,%1,%2,%3}, [%4];"
                 : "=r"(r[0]), "=r"(r[1]), "=r"(r[2]), "=r"(r[3]) : "r"(addr));
}
__device__ __forceinline__ void ldsm_x4_t(uint32_t addr, uint32_t* r) {
    asm volatile("ldmatrix.sync.aligned.m8n8.x4.trans.shared.b16 {%0,%1,%2,%3}, [%4];"
                 : "=r"(r[0]), "=r"(r[1]), "=r"(r[2]), "=r"(r[3]) : "r"(addr));
}
__device__ __forceinline__ void mma_bf16(float* c, const uint32_t* a,
                                         uint32_t b0, uint32_t b1) {
    asm volatile(
        "mma.sync.aligned.m16n8k16.row.col.f32.bf16.bf16.f32 "
        "{%0,%1,%2,%3}, {%4,%5,%6,%7}, {%8,%9}, {%0,%1,%2,%3};"
        : "+f"(c[0]), "+f"(c[1]), "+f"(c[2]), "+f"(c[3])
        : "r"(a[0]), "r"(a[1]), "r"(a[2]), "r"(a[3]), "r"(b0), "r"(b1));
}

// ---- fast grid barrier: red-arrive + spin on monotonic counter ---------------
// g_count is zeroed by init_kernel at the start of every kernel_launch, so the
// per-thread 'target' register (starting at 0) matches across graph replays.
__device__ __forceinline__ void grid_barrier(unsigned& target) {
    __syncthreads();
    if (threadIdx.x == 0) {
        __threadfence();   // release: prior writes visible before arrival
        asm volatile("red.global.gpu.add.u32 [%0], 1;"
                     :: "l"(&g_count) : "memory");
        target += GRID;
        unsigned v;
        do {
            asm volatile("ld.acquire.gpu.u32 %0, [%1];" : "=r"(v) : "l"(&g_count));
        } while ((int)(v - target) < 0);
        __threadfence();   // extend acquire ordering
    }
    __syncthreads();
}

__global__ void init_kernel() { g_count = 0u; }

extern __shared__ float smem[];

// -----------------------------------------------------------------------------
// Persistent scan kernel (256 threads, R4 config): all 256 steps in one launch.
// CTA (nb, kb) keeps W_hh[kb*128:+128, nb*256:+256] resident in SMEM.
// -----------------------------------------------------------------------------
__global__ void __launch_bounds__(SCTHREADS) scan_kernel(
    const float* __restrict__ state,
    const float* __restrict__ W,
    float* __restrict__ out)
{
    float* ws = smem;                       // [KSL][NSL]
    float* hsb = smem + KSL * NSL;          // [2][64][68]
    const int HPAD = 68;
    const int HBUF = 64 * HPAD;

    const int tid = threadIdx.x;
    const int cta = blockIdx.x;
    const int nb = cta & (NBD - 1);
    const int kb = cta >> 3;
    const int nbase = nb * NSL;
    const int k0 = kb * KSL;
    const int tx = tid & 15;                // n: 4 quads at q*64 + tx*4
    const int ty = tid >> 4;                // 0..15 -> m rows ty*4..+3

    // load resident W slice (once)
#pragma unroll
    for (int i = 0; i < 32; i++) {
        int idx = i * SCTHREADS + tid;      // 0..8191 float4s
        int k = idx >> 6;
        int c4 = (idx & 63) * 4;
        *(float4*)&ws[k * NSL + c4] =
            *(const float4*)&W[(size_t)(k0 + k) * HH + nbase + c4];
    }
    __syncthreads();

    unsigned target = 0;   // barrier epoch target (g_count zeroed per launch)

    // epilogue mapping: 128*256 threads == 32768 float4 slots exactly
    const int g = cta * SCTHREADS + tid;
    const int em = g >> 9;
    const int ec4 = (g & 511) * 4;
    const size_t eoff = (size_t)em * HH + ec4;

    for (int t = 0; t < TT; t++) {
        const float* hp = (t == 0) ? state : (out + (size_t)(t - 1) * STEP_ELEMS);

        ull acc[4][8];
#pragma unroll
        for (int i = 0; i < 4; i++)
#pragma unroll
            for (int j = 0; j < 8; j++) acc[i][j] = 0ULL;

        // prefetch chunk 0 of h (64 k x 64 m)
        float4 hreg[4];
#pragma unroll
        for (int i = 0; i < 4; i++) {
            int idx = i * SCTHREADS + tid;  // 0..1023
            int m = idx >> 4, kq4 = (idx & 15) * 4;
            hreg[i] = __ldcg((const float4*)&hp[(size_t)m * HH + k0 + kq4]);
        }

        int buf = 0;
        for (int c = 0; c < KSL / 64; c++) {     // 2 chunks
#pragma unroll
            for (int i = 0; i < 4; i++) {
                int idx = i * SCTHREADS + tid;
                int m = idx >> 4, kq4 = (idx & 15) * 4;
                *(float4*)&hsb[buf * HBUF + m * HPAD + kq4] = hreg[i];
            }
            __syncthreads();
            if (c + 1 < KSL / 64) {
#pragma unroll
                for (int i = 0; i < 4; i++) {
                    int idx = i * SCTHREADS + tid;
                    int m = idx >> 4, kq4 = (idx & 15) * 4;
                    hreg[i] = __ldcg((const float4*)&hp[(size_t)m * HH + k0 + (c + 1) * 64 + kq4]);
                }
            }
            const float* hb = hsb + buf * HBUF + (ty * 4) * HPAD;
            const float* wrow = ws + (c * 64) * NSL + tx * 4;
#pragma unroll 8
            for (int kk = 0; kk < 64; kk++) {
                const float* wr = wrow + kk * NSL;
                ulonglong2 b0 = *(const ulonglong2*)(wr);
                ulonglong2 b1 = *(const ulonglong2*)(wr + 64);
                ulonglong2 b2 = *(const ulonglong2*)(wr + 128);
                ulonglong2 b3 = *(const ulonglong2*)(wr + 192);
                float a0 = hb[kk];
                float a1 = hb[HPAD + kk];
                float a2 = hb[2 * HPAD + kk];
                float a3 = hb[3 * HPAD + kk];
                ull A0 = pack2(a0, a0), A1 = pack2(a1, a1);
                ull A2 = pack2(a2, a2), A3 = pack2(a3, a3);
#define FM(i, A)                                    \
                fma2(acc[i][0], A, b0.x); fma2(acc[i][1], A, b0.y); \
                fma2(acc[i][2], A, b1.x); fma2(acc[i][3], A, b1.y); \
                fma2(acc[i][4], A, b2.x); fma2(acc[i][5], A, b2.y); \
                fma2(acc[i][6], A, b3.x); fma2(acc[i][7], A, b3.y)
                FM(0, A0); FM(1, A1); FM(2, A2); FM(3, A3);
#undef FM
            }
            __syncthreads();
            buf ^= 1;
        }

        // write partial tile [64 x 256] to g_part[kb]
        float* P = g_part + (size_t)kb * STEP_ELEMS;
#pragma unroll
        for (int i = 0; i < 4; i++) {
            const int m = ty * 4 + i;
#pragma unroll
            for (int q = 0; q < 4; q++) {
                float4 v;
                unpack2(acc[i][2 * q + 0], v.x, v.y);
                unpack2(acc[i][2 * q + 1], v.z, v.w);
                *(float4*)&P[(size_t)m * HH + nbase + q * 64 + tx * 4] = v;
            }
        }
        grid_barrier(target);

        // distributed epilogue: reduce 16 partials + x_proj, tanh -> out[t]
        {
            float4 s = __ldcg((const float4*)&g_part[eoff]);
#pragma unroll
            for (int k2 = 1; k2 < KBD; k2++) {
                float4 p = __ldcg((const float4*)&g_part[(size_t)k2 * STEP_ELEMS + eoff]);
                s.x += p.x; s.y += p.y; s.z += p.z; s.w += p.w;
            }
            const float4 xv = *(const float4*)&g_xproj[(size_t)t * STEP_ELEMS + eoff];
            float4 r;
            r.x = tanhf(s.x + xv.x);
            r.y = tanhf(s.y + xv.y);
            r.z = tanhf(s.z + xv.z);
            r.w = tanhf(s.w + xv.w);
            *(float4*)&out[(size_t)t * STEP_ELEMS + eoff] = r;
            if (t == TT - 1)
                *(float4*)&out[(size_t)TT * STEP_ELEMS + eoff] = r;   // final_state
        }
        grid_barrier(target);
    }
}

// -----------------------------------------------------------------------------
// Elementwise bf16 hi/lo split: hi = bf16(x), lo = bf16(x - hi)
// -----------------------------------------------------------------------------
__global__ void __launch_bounds__(256) convert_split(
    const float* __restrict__ src,
    __nv_bfloat16* __restrict__ hi,
    __nv_bfloat16* __restrict__ lo)
{
    const int i = blockIdx.x * 256 + threadIdx.x;
    float4 v = ((const float4*)src)[i];
    float s[4] = {v.x, v.y, v.z, v.w};
    __nv_bfloat16 h[4], l[4];
#pragma unroll
    for (int j = 0; j < 4; j++) {
        h[j] = __float2bfloat16(s[j]);
        l[j] = __float2bfloat16(s[j] - __bfloat162float(h[j]));
    }
    __nv_bfloat162 h01 = __halves2bfloat162(h[0], h[1]);
    __nv_bfloat162 h23 = __halves2bfloat162(h[2], h[3]);
    __nv_bfloat162 l01 = __halves2bfloat162(l[0], l[1]);
    __nv_bfloat162 l23 = __halves2bfloat162(l[2], l[3]);
    ((uint2*)hi)[i] = make_uint2(*(uint32_t*)&h01, *(uint32_t*)&h23);
    ((uint2*)lo)[i] = make_uint2(*(uint32_t*)&l01, *(uint32_t*)&l23);
}

// -----------------------------------------------------------------------------
// x_proj via mma.sync bf16-split: D = Xhi*Whi + Xhi*Wlo + Xlo*Whi (+bias)
// CTA tile [128m x 128n], 8 warps (2m x 4n), warp tile 64x32, k-chunk 32.
// -----------------------------------------------------------------------------
#define APAD 40    // bf16 per A smem row (80 B, conflict-free ldmatrix)
#define BPAD 136   // bf16 per B smem row (272 B, conflict-free ldmatrix)

__global__ void __launch_bounds__(256) xproj_mma(
    const __nv_bfloat16* __restrict__ Xhi,
    const __nv_bfloat16* __restrict__ Xlo,
    const __nv_bfloat16* __restrict__ Whi,
    const __nv_bfloat16* __restrict__ Wlo,
    const float* __restrict__ bias)
{
    __shared__ __align__(16) __nv_bfloat16 sa[2][128 * APAD];   // hi, lo
    __shared__ __align__(16) __nv_bfloat16 sb[2][32 * BPAD];

    const int tid = threadIdx.x;
    const int wid = tid >> 5;
    const int lane = tid & 31;
    const int nbase = blockIdx.x * 128;
    const int mbase = blockIdx.y * 128;
    const int wm = (wid & 1) * 64;
    const int wn = (wid >> 1) * 32;

    float c[4][4][4];
#pragma unroll
    for (int mi = 0; mi < 4; mi++)
#pragma unroll
        for (int j = 0; j < 4; j++)
#pragma unroll
            for (int q = 0; q < 4; q++) c[mi][j][q] = 0.0f;

    uint4 pa[2][2], pb[2][2];
    const __nv_bfloat16* Xs[2] = {Xhi, Xlo};
    const __nv_bfloat16* Ws[2] = {Whi, Wlo};

    // prefetch chunk 0
#pragma unroll
    for (int v = 0; v < 2; v++) {
#pragma unroll
        for (int it = 0; it < 2; it++) {
            int idx = it * 256 + tid;            // 0..511
            int r = idx >> 2, c8 = (idx & 3) * 8;
            pa[v][it] = *(const uint4*)&Xs[v][(size_t)(mbase + r) * DD + c8];
            int kr = idx >> 4, n8 = (idx & 15) * 8;
            pb[v][it] = *(const uint4*)&Ws[v][(size_t)kr * HH + nbase + n8];
        }
    }

    const int lrow = lane & 15;
    const int lcolq = lane >> 4;   // 0 or 1

    for (int ch = 0; ch < DD / 32; ch++) {       // 32 chunks of k=32
#pragma unroll
        for (int v = 0; v < 2; v++) {
#pragma unroll
            for (int it = 0; it < 2; it++) {
                int idx = it * 256 + tid;
                int r = idx >> 2, c8 = (idx & 3) * 8;
                *(uint4*)&sa[v][r * APAD + c8] = pa[v][it];
                int kr = idx >> 4, n8 = (idx & 15) * 8;
                *(uint4*)&sb[v][kr * BPAD + n8] = pb[v][it];
            }
        }
        __syncthreads();
        if (ch + 1 < DD / 32) {
            const int kc = (ch + 1) * 32;
#pragma unroll
            for (int v = 0; v < 2; v++) {
#pragma unroll
                for (int it = 0; it < 2; it++) {
                    int idx = it * 256 + tid;
                    int r = idx >> 2, c8 = (idx & 3) * 8;
                    pa[v][it] = *(const uint4*)&Xs[v][(size_t)(mbase + r) * DD + kc + c8];
                    int kr = idx >> 4, n8 = (idx & 15) * 8;
                    pb[v][it] = *(const uint4*)&Ws[v][(size_t)(kc + kr) * HH + nbase + n8];
                }
            }
        }

#pragma unroll
        for (int ks = 0; ks < 2; ks++) {         // two k16 steps
            uint32_t ah[4][4], al[4][4];
#pragma unroll
            for (int mi = 0; mi < 4; mi++) {
                uint32_t off = (uint32_t)((wm + mi * 16 + lrow) * APAD +
                                          ks * 16 + lcolq * 8) * 2;
                ldsm_x4(smem_to_u32(&sa[0][0]) + off, ah[mi]);
                ldsm_x4(smem_to_u32(&sa[1][0]) + off, al[mi]);
            }
            uint32_t bh[2][4], bl[2][4];
#pragma unroll
            for (int np = 0; np < 2; np++) {
                uint32_t off = (uint32_t)((ks * 16 + lrow) * BPAD +
                                          wn + np * 16 + lcolq * 8) * 2;
                ldsm_x4_t(smem_to_u32(&sb[0][0]) + off, bh[np]);
                ldsm_x4_t(smem_to_u32(&sb[1][0]) + off, bl[np]);
            }
#pragma unroll
            for (int mi = 0; mi < 4; mi++) {
#pragma unroll
                for (int j = 0; j < 4; j++) {
                    const int np = j >> 1, pr = (j & 1) * 2;
                    mma_bf16(c[mi][j], ah[mi], bh[np][pr], bh[np][pr + 1]);
                    mma_bf16(c[mi][j], ah[mi], bl[np][pr], bl[np][pr + 1]);
                    mma_bf16(c[mi][j], al[mi], bh[np][pr], bh[np][pr + 1]);
                }
            }
        }
        __syncthreads();
    }

    // epilogue: c[mi][j] -> g_xproj (+bias)
#pragma unroll
    for (int mi = 0; mi < 4; mi++) {
        const int row0 = mbase + wm + mi * 16 + (lane >> 2);
#pragma unroll
        for (int j = 0; j < 4; j++) {
            const int col = nbase + wn + j * 8 + (lane & 3) * 2;
            const float b0 = __ldg(&bias[col]);
            const float b1 = __ldg(&bias[col + 1]);
            float2 v0 = make_float2(c[mi][j][0] + b0, c[mi][j][1] + b1);
            float2 v1 = make_float2(c[mi][j][2] + b0, c[mi][j][3] + b1);
            *(float2*)&g_xproj[(size_t)row0 * HH + col] = v0;
            *(float2*)&g_xproj[(size_t)(row0 + 8) * HH + col] = v1;
        }
    }
}

extern "C" void kernel_launch(void* const* d_in, const int* in_sizes, int n_in,
                              void* d_out, int out_size)
{
    (void)in_sizes; (void)n_in; (void)out_size;
    const float* inputs = (const float*)d_in[0];   // [T,B,D]
    const float* state  = (const float*)d_in[1];   // [B,H]
    const float* W_xh   = (const float*)d_in[2];   // [D,H]
    const float* W_hh   = (const float*)d_in[3];   // [H,H]
    const float* b_h    = (const float*)d_in[4];   // [H]
    float* out = (float*)d_out;   // outputs [T,B,H] then final_state [B,H]

    const int sc_smem = (KSL * NSL + 2 * 64 * 68) * sizeof(float);  // 165888
    cudaFuncSetAttribute(scan_kernel, cudaFuncAttributeMaxDynamicSharedMemorySize,
                         sc_smem);

    __nv_bfloat16 *xhi, *xlo, *whi, *wlo;
    cudaGetSymbolAddress((void**)&xhi, g_xhi);
    cudaGetSymbolAddress((void**)&xlo, g_xlo);
    cudaGetSymbolAddress((void**)&whi, g_whi);
    cudaGetSymbolAddress((void**)&wlo, g_wlo);

    // 0) reset barrier counter (deterministic across graph replays)
    init_kernel<<<1, 1>>>();

    // 1) bf16 hi/lo splits of X and W_xh
    convert_split<<<(TT * BB * DD / 4) / 256, 256>>>(inputs, xhi, xlo);
    convert_split<<<(DD * HH / 4) / 256, 256>>>(W_xh, whi, wlo);

    // 2) x_proj via tensor cores (mma.sync bf16-split)
    xproj_mma<<<dim3(HH / 128, (TT * BB) / 128), 256>>>(xhi, xlo, whi, wlo, b_h);

    // 3) persistent scan: all 256 steps in one launch
    scan_kernel<<<GRID, SCTHREADS, sc_smem>>>(state, W_hh, out);
}

// round 9
// speedup vs baseline: 2.3677x; 1.6722x over previous
#include <cuda_runtime.h>
#include <cuda_bf16.h>
#include <math.h>
#include <stdint.h>

#define TT 256
#define BB 64
#define DD 1024
#define HH 2048

#define GRID 128
#define SCTHREADS 256
#define NBD 8            // n-blocks (each 256 wide)
#define KBD 16           // k-blocks (each 128 deep)
#define NSL 256
#define KSL 128
#define STEP_ELEMS (BB * HH)   // 131072

typedef unsigned long long ull;

// Scratch (no cudaMalloc allowed)
__device__ __align__(16) float g_xproj[(size_t)TT * BB * HH];     // 128 MB
__device__ __align__(16) float g_part[(size_t)KBD * BB * HH];     // 8 MB
__device__ __align__(16) __nv_bfloat16 g_xhi[(size_t)TT * BB * DD];
__device__ __align__(16) __nv_bfloat16 g_xlo[(size_t)TT * BB * DD];
__device__ __align__(16) __nv_bfloat16 g_whi[(size_t)DD * HH];
__device__ __align__(16) __nv_bfloat16 g_wlo[(size_t)DD * HH];
__device__ unsigned g_count;     // monotonic arrival counter (zeroed per launch)

__device__ __forceinline__ uint32_t smem_to_u32(const void* p) {
    uint32_t a;
    asm("{ .reg .u64 t; cvta.to.shared.u64 t, %1; cvt.u32.u64 %0, t; }"
        : "=r"(a) : "l"(p));
    return a;
}

// ---- mma.sync helpers (sm_80-era PTX, compiles for compute_103) --------------
__device__ __forceinline__ void ldsm_x4(uint32_t addr, uint32_t* r) {
    asm volatile("ldmatrix.sync.aligned.m8n8.x4.shared.b16 {%0,%1,%2,%3}, [%4];"
                 : "=r"(r[0]), "=r"(r[1]), "=r"(r[2]), "=r"(r[3]) : "r"(addr));
}
__device__ __forceinline__ void ldsm_x4_t(uint32_t addr, uint32_t* r) {
    asm volatile("ldmatrix.sync.aligned.m8n8.x4.trans.shared.b16 {%0,%1,%2,%3}, [%4];"
                 : "=r"(r[0]), "=r"(r[1]), "=r"(r[2]), "=r"(r[3]) : "r"(addr));
}
__device__ __forceinline__ void mma_bf16(float* c, const uint32_t* a,
                                         uint32_t b0, uint32_t b1) {
    asm volatile(
        "mma.sync.aligned.m16n8k16.row.col.f32.bf16.bf16.f32 "
        "{%0,%1,%2,%3}, {%4,%5,%6,%7}, {%8,%9}, {%0,%1,%2,%3};"
        : "+f"(c[0]), "+f"(c[1]), "+f"(c[2]), "+f"(c[3])
        : "r"(a[0]), "r"(a[1]), "r"(a[2]), "r"(a[3]), "r"(b0), "r"(b1));
}

// hi/lo split of 4 floats into packed bf16x2 pairs
__device__ __forceinline__ void split4(const float4& v, uint2& hi, uint2& lo) {
    float s[4] = {v.x, v.y, v.z, v.w};
    __nv_bfloat16 h[4], l[4];
#pragma unroll
    for (int j = 0; j < 4; j++) {
        h[j] = __float2bfloat16(s[j]);
        l[j] = __float2bfloat16(s[j] - __bfloat162float(h[j]));
    }
    __nv_bfloat162 h01 = __halves2bfloat162(h[0], h[1]);
    __nv_bfloat162 h23 = __halves2bfloat162(h[2], h[3]);
    __nv_bfloat162 l01 = __halves2bfloat162(l[0], l[1]);
    __nv_bfloat162 l23 = __halves2bfloat162(l[2], l[3]);
    hi = make_uint2(*(uint32_t*)&h01, *(uint32_t*)&h23);
    lo = make_uint2(*(uint32_t*)&l01, *(uint32_t*)&l23);
}

// ---- fast grid barrier: red-arrive + spin on monotonic counter ---------------
__device__ __forceinline__ void grid_barrier(unsigned& target) {
    __syncthreads();
    if (threadIdx.x == 0) {
        __threadfence();
        asm volatile("red.global.gpu.add.u32 [%0], 1;"
                     :: "l"(&g_count) : "memory");
        target += GRID;
        unsigned v;
        do {
            asm volatile("ld.acquire.gpu.u32 %0, [%1];" : "=r"(v) : "l"(&g_count));
        } while ((int)(v - target) < 0);
        __threadfence();
    }
    __syncthreads();
}

__global__ void init_kernel() { g_count = 0u; }

extern __shared__ float smem[];

// -----------------------------------------------------------------------------
// Persistent tensor-core scan: all 256 steps in one launch.
// CTA (nb, kb): resident bf16 hi/lo of W_hh[kb*128:+128, nb*256:+256] in SMEM.
// Per step: convert h slice -> SMEM bf16 hi/lo; 3-term bf16-split mma to a
// [64x256] fp32 partial -> g_part[kb]; barrier; 16-way reduce + xproj + tanh.
// -----------------------------------------------------------------------------
#define BP 264      // bf16 per W smem row (528 B; 528 % 128 == 16, conflict-free)
#define AP 136      // bf16 per h smem row (272 B; same residue)
#define SB_HI 0
#define SB_LO (SB_HI + KSL * BP * 2)          // 67584
#define SA_HI (SB_LO + KSL * BP * 2)          // 135168
#define SA_LO (SA_HI + BB * AP * 2)           // 152576
#define SC_SMEM (SA_LO + BB * AP * 2)         // 169984 bytes

__global__ void __launch_bounds__(SCTHREADS) scan_kernel(
    const float* __restrict__ state,
    const float* __restrict__ W,
    float* __restrict__ out)
{
    char* sm = (char*)smem;
    __nv_bfloat16* sbh = (__nv_bfloat16*)(sm + SB_HI);
    __nv_bfloat16* sbl = (__nv_bfloat16*)(sm + SB_LO);
    __nv_bfloat16* sah = (__nv_bfloat16*)(sm + SA_HI);
    __nv_bfloat16* sal = (__nv_bfloat16*)(sm + SA_LO);

    const int tid = threadIdx.x;
    const int cta = blockIdx.x;
    const int nb = cta & (NBD - 1);
    const int kb = cta >> 3;
    const int nbase = nb * NSL;
    const int k0 = kb * KSL;
    const int wid = tid >> 5;
    const int lane = tid & 31;
    const int wn = wid * 32;          // warp's 32-col n slice
    const int lrow = lane & 15;
    const int lcolq = lane >> 4;      // 0 or 1

    const uint32_t sbh_b = smem_to_u32(sbh);
    const uint32_t sbl_b = smem_to_u32(sbl);
    const uint32_t sah_b = smem_to_u32(sah);
    const uint32_t sal_b = smem_to_u32(sal);

    // ---- load + split resident W slice [128k x 256n] (once) ----
#pragma unroll
    for (int i = 0; i < 32; i++) {
        int idx = i * SCTHREADS + tid;      // 0..8191 float4
        int k = idx >> 6;
        int n4 = (idx & 63) * 4;
        float4 w = *(const float4*)&W[(size_t)(k0 + k) * HH + nbase + n4];
        uint2 hi, lo;
        split4(w, hi, lo);
        *(uint2*)&sbh[k * BP + n4] = hi;
        *(uint2*)&sbl[k * BP + n4] = lo;
    }
    __syncthreads();

    unsigned target = 0;

    // epilogue mapping: 128*256 threads == 32768 float4 slots exactly
    const int g = cta * SCTHREADS + tid;
    const int em = g >> 9;
    const int ec4 = (g & 511) * 4;
    const size_t eoff = (size_t)em * HH + ec4;

    for (int t = 0; t < TT; t++) {
        const float* hp = (t == 0) ? state : (out + (size_t)(t - 1) * STEP_ELEMS);

        // ---- stage h slice [64m x 128k] -> bf16 hi/lo SMEM ----
#pragma unroll
        for (int i = 0; i < 8; i++) {
            int idx = i * SCTHREADS + tid;  // 0..2047 float4
            int m = idx >> 5;
            int k4 = (idx & 31) * 4;
            float4 h = __ldcg((const float4*)&hp[(size_t)m * HH + k0 + k4]);
            uint2 hi, lo;
            split4(h, hi, lo);
            *(uint2*)&sah[m * AP + k4] = hi;
            *(uint2*)&sal[m * AP + k4] = lo;
        }
        __syncthreads();

        // ---- mma mainloop: 8 k16 steps over the 128k slice ----
        float c[4][4][4];
#pragma unroll
        for (int mi = 0; mi < 4; mi++)
#pragma unroll
            for (int j = 0; j < 4; j++)
#pragma unroll
                for (int q = 0; q < 4; q++) c[mi][j][q] = 0.0f;

#pragma unroll
        for (int ks = 0; ks < 8; ks++) {
            uint32_t ah[4][4], al[4][4];
#pragma unroll
            for (int mi = 0; mi < 4; mi++) {
                uint32_t off = (uint32_t)((mi * 16 + lrow) * AP +
                                          ks * 16 + lcolq * 8) * 2;
                ldsm_x4(sah_b + off, ah[mi]);
                ldsm_x4(sal_b + off, al[mi]);
            }
            uint32_t bh[2][4], bl[2][4];
#pragma unroll
            for (int np = 0; np < 2; np++) {
                uint32_t off = (uint32_t)((ks * 16 + lrow) * BP +
                                          wn + np * 16 + lcolq * 8) * 2;
                ldsm_x4_t(sbh_b + off, bh[np]);
                ldsm_x4_t(sbl_b + off, bl[np]);
            }
#pragma unroll
            for (int mi = 0; mi < 4; mi++) {
#pragma unroll
                for (int j = 0; j < 4; j++) {
                    const int np = j >> 1, pr = (j & 1) * 2;
                    mma_bf16(c[mi][j], ah[mi], bh[np][pr], bh[np][pr + 1]);
                    mma_bf16(c[mi][j], ah[mi], bl[np][pr], bl[np][pr + 1]);
                    mma_bf16(c[mi][j], al[mi], bh[np][pr], bh[np][pr + 1]);
                }
            }
        }

        // ---- write partial [64 x 256] to g_part[kb] ----
        float* P = g_part + (size_t)kb * STEP_ELEMS;
#pragma unroll
        for (int mi = 0; mi < 4; mi++) {
            const int row0 = mi * 16 + (lane >> 2);
#pragma unroll
            for (int j = 0; j < 4; j++) {
                const int col = nbase + wn + j * 8 + (lane & 3) * 2;
                *(float2*)&P[(size_t)row0 * HH + col] =
                    make_float2(c[mi][j][0], c[mi][j][1]);
                *(float2*)&P[(size_t)(row0 + 8) * HH + col] =
                    make_float2(c[mi][j][2], c[mi][j][3]);
            }
        }
        grid_barrier(target);

        // ---- distributed epilogue: reduce 16 partials + xproj, tanh ----
        {
            float4 s = __ldcg((const float4*)&g_part[eoff]);
#pragma unroll
            for (int k2 = 1; k2 < KBD; k2++) {
                float4 p = __ldcg((const float4*)&g_part[(size_t)k2 * STEP_ELEMS + eoff]);
                s.x += p.x; s.y += p.y; s.z += p.z; s.w += p.w;
            }
            const float4 xv = *(const float4*)&g_xproj[(size_t)t * STEP_ELEMS + eoff];
            float4 r;
            r.x = tanhf(s.x + xv.x);
            r.y = tanhf(s.y + xv.y);
            r.z = tanhf(s.z + xv.z);
            r.w = tanhf(s.w + xv.w);
            *(float4*)&out[(size_t)t * STEP_ELEMS + eoff] = r;
            if (t == TT - 1)
                *(float4*)&out[(size_t)TT * STEP_ELEMS + eoff] = r;   // final_state
        }
        grid_barrier(target);
    }
}

// -----------------------------------------------------------------------------
// Elementwise bf16 hi/lo split: hi = bf16(x), lo = bf16(x - hi)
// -----------------------------------------------------------------------------
__global__ void __launch_bounds__(256) convert_split(
    const float* __restrict__ src,
    __nv_bfloat16* __restrict__ hi,
    __nv_bfloat16* __restrict__ lo)
{
    const int i = blockIdx.x * 256 + threadIdx.x;
    float4 v = ((const float4*)src)[i];
    uint2 h, l;
    split4(v, h, l);
    ((uint2*)hi)[i] = h;
    ((uint2*)lo)[i] = l;
}

// -----------------------------------------------------------------------------
// x_proj via mma.sync bf16-split (validated R6/R7 kernel, unchanged)
// -----------------------------------------------------------------------------
#define APAD 40    // bf16 per A smem row (80 B, conflict-free ldmatrix)
#define BPAD 136   // bf16 per B smem row (272 B, conflict-free ldmatrix)

__global__ void __launch_bounds__(256) xproj_mma(
    const __nv_bfloat16* __restrict__ Xhi,
    const __nv_bfloat16* __restrict__ Xlo,
    const __nv_bfloat16* __restrict__ Whi,
    const __nv_bfloat16* __restrict__ Wlo,
    const float* __restrict__ bias)
{
    __shared__ __align__(16) __nv_bfloat16 sa[2][128 * APAD];   // hi, lo
    __shared__ __align__(16) __nv_bfloat16 sb[2][32 * BPAD];

    const int tid = threadIdx.x;
    const int wid = tid >> 5;
    const int lane = tid & 31;
    const int nbase = blockIdx.x * 128;
    const int mbase = blockIdx.y * 128;
    const int wm = (wid & 1) * 64;
    const int wn = (wid >> 1) * 32;

    float c[4][4][4];
#pragma unroll
    for (int mi = 0; mi < 4; mi++)
#pragma unroll
        for (int j = 0; j < 4; j++)
#pragma unroll
            for (int q = 0; q < 4; q++) c[mi][j][q] = 0.0f;

    uint4 pa[2][2], pb[2][2];
    const __nv_bfloat16* Xs[2] = {Xhi, Xlo};
    const __nv_bfloat16* Ws[2] = {Whi, Wlo};

#pragma unroll
    for (int v = 0; v < 2; v++) {
#pragma unroll
        for (int it = 0; it < 2; it++) {
            int idx = it * 256 + tid;
            int r = idx >> 2, c8 = (idx & 3) * 8;
            pa[v][it] = *(const uint4*)&Xs[v][(size_t)(mbase + r) * DD + c8];
            int kr = idx >> 4, n8 = (idx & 15) * 8;
            pb[v][it] = *(const uint4*)&Ws[v][(size_t)kr * HH + nbase + n8];
        }
    }

    const int lrow = lane & 15;
    const int lcolq = lane >> 4;

    for (int ch = 0; ch < DD / 32; ch++) {
#pragma unroll
        for (int v = 0; v < 2; v++) {
#pragma unroll
            for (int it = 0; it < 2; it++) {
                int idx = it * 256 + tid;
                int r = idx >> 2, c8 = (idx & 3) * 8;
                *(uint4*)&sa[v][r * APAD + c8] = pa[v][it];
                int kr = idx >> 4, n8 = (idx & 15) * 8;
                *(uint4*)&sb[v][kr * BPAD + n8] = pb[v][it];
            }
        }
        __syncthreads();
        if (ch + 1 < DD / 32) {
            const int kc = (ch + 1) * 32;
#pragma unroll
            for (int v = 0; v < 2; v++) {
#pragma unroll
                for (int it = 0; it < 2; it++) {
                    int idx = it * 256 + tid;
                    int r = idx >> 2, c8 = (idx & 3) * 8;
                    pa[v][it] = *(const uint4*)&Xs[v][(size_t)(mbase + r) * DD + kc + c8];
                    int kr = idx >> 4, n8 = (idx & 15) * 8;
                    pb[v][it] = *(const uint4*)&Ws[v][(size_t)(kc + kr) * HH + nbase + n8];
                }
            }
        }

#pragma unroll
        for (int ks = 0; ks < 2; ks++) {
            uint32_t ah[4][4], al[4][4];
#pragma unroll
            for (int mi = 0; mi < 4; mi++) {
                uint32_t off = (uint32_t)((wm + mi * 16 + lrow) * APAD +
                                          ks * 16 + lcolq * 8) * 2;
                ldsm_x4(smem_to_u32(&sa[0][0]) + off, ah[mi]);
                ldsm_x4(smem_to_u32(&sa[1][0]) + off, al[mi]);
            }
            uint32_t bh[2][4], bl[2][4];
#pragma unroll
            for (int np = 0; np < 2; np++) {
                uint32_t off = (uint32_t)((ks * 16 + lrow) * BPAD +
                                          wn + np * 16 + lcolq * 8) * 2;
                ldsm_x4_t(smem_to_u32(&sb[0][0]) + off, bh[np]);
                ldsm_x4_t(smem_to_u32(&sb[1][0]) + off, bl[np]);
            }
#pragma unroll
            for (int mi = 0; mi < 4; mi++) {
#pragma unroll
                for (int j = 0; j < 4; j++) {
                    const int np = j >> 1, pr = (j & 1) * 2;
                    mma_bf16(c[mi][j], ah[mi], bh[np][pr], bh[np][pr + 1]);
                    mma_bf16(c[mi][j], ah[mi], bl[np][pr], bl[np][pr + 1]);
                    mma_bf16(c[mi][j], al[mi], bh[np][pr], bh[np][pr + 1]);
                }
            }
        }
        __syncthreads();
    }

#pragma unroll
    for (int mi = 0; mi < 4; mi++) {
        const int row0 = mbase + wm + mi * 16 + (lane >> 2);
#pragma unroll
        for (int j = 0; j < 4; j++) {
            const int col = nbase + wn + j * 8 + (lane & 3) * 2;
            const float b0 = __ldg(&bias[col]);
            const float b1 = __ldg(&bias[col + 1]);
            float2 v0 = make_float2(c[mi][j][0] + b0, c[mi][j][1] + b1);
            float2 v1 = make_float2(c[mi][j][2] + b0, c[mi][j][3] + b1);
            *(float2*)&g_xproj[(size_t)row0 * HH + col] = v0;
            *(float2*)&g_xproj[(size_t)(row0 + 8) * HH + col] = v1;
        }
    }
}

extern "C" void kernel_launch(void* const* d_in, const int* in_sizes, int n_in,
                              void* d_out, int out_size)
{
    (void)in_sizes; (void)n_in; (void)out_size;
    const float* inputs = (const float*)d_in[0];   // [T,B,D]
    const float* state  = (const float*)d_in[1];   // [B,H]
    const float* W_xh   = (const float*)d_in[2];   // [D,H]
    const float* W_hh   = (const float*)d_in[3];   // [H,H]
    const float* b_h    = (const float*)d_in[4];   // [H]
    float* out = (float*)d_out;   // outputs [T,B,H] then final_state [B,H]

    cudaFuncSetAttribute(scan_kernel, cudaFuncAttributeMaxDynamicSharedMemorySize,
                         SC_SMEM);

    __nv_bfloat16 *xhi, *xlo, *whi, *wlo;
    cudaGetSymbolAddress((void**)&xhi, g_xhi);
    cudaGetSymbolAddress((void**)&xlo, g_xlo);
    cudaGetSymbolAddress((void**)&whi, g_whi);
    cudaGetSymbolAddress((void**)&wlo, g_wlo);

    // 0) reset barrier counter (deterministic across graph replays)
    init_kernel<<<1, 1>>>();

    // 1) bf16 hi/lo splits of X and W_xh
    convert_split<<<(TT * BB * DD / 4) / 256, 256>>>(inputs, xhi, xlo);
    convert_split<<<(DD * HH / 4) / 256, 256>>>(W_xh, whi, wlo);

    // 2) x_proj via tensor cores (mma.sync bf16-split)
    xproj_mma<<<dim3(HH / 128, (TT * BB) / 128), 256>>>(xhi, xlo, whi, wlo, b_h);

    // 3) persistent tensor-core scan: all 256 steps in one launch
    scan_kernel<<<GRID, SCTHREADS, SC_SMEM>>>(state, W_hh, out);
}